// round 11
// baseline (speedup 1.0000x reference)
#include <cuda_runtime.h>
#include <cuda_bf16.h>
#include <cstdint>
#include <math.h>

// Problem constants
#define O_NODES 10000
#define T_EDGES 50000
#define HH      512
#define NG      2048
#define HIST_SZ 131072

// ---------------- scratch (__device__ globals) --------------------------------
// bf16 hi/lo operand buffers: [rows][2K] = hi cols 0..K-1, lo cols K..2K-1
__device__ __nv_bfloat16 g_curhl [(size_t)T_EDGES * 768];
__device__ __nv_bfloat16 g_midhl [(size_t)T_EDGES * 1024];
__device__ __nv_bfloat16 g_shl   [(size_t)T_EDGES * 1024];
__device__ __nv_bfloat16 g_ohl   [(size_t)T_EDGES * 1024];
__device__ __nv_bfloat16 g_objhl [(size_t)O_NODES * 256];
__device__ __nv_bfloat16 g_prevhl[(size_t)O_NODES * 1024];
__device__ __nv_bfloat16 g_hsA   [(size_t)O_NODES * 1024];  // h ping-pong (hilo)
__device__ __nv_bfloat16 g_hsB   [(size_t)O_NODES * 1024];
__device__ __nv_bfloat16 g_pchl  [(size_t)O_NODES * 2048];
// fp32 state / results
__device__ float g_gxs [(size_t)T_EDGES * NG];
__device__ float g_gxo [(size_t)T_EDGES * NG];
__device__ float g_cs  [(size_t)O_NODES * HH];
// weights hilo (Wih/Whh gate-permuted)
__device__ __nv_bfloat16 g_w1hl   [512  * 768];
__device__ __nv_bfloat16 g_w2hl   [1152 * 1024];
__device__ __nv_bfloat16 g_wihhl  [2048 * 1024];
__device__ __nv_bfloat16 g_whhhl  [2048 * 1024];
__device__ __nv_bfloat16 g_wprojhl[512  * 256];
__device__ __nv_bfloat16 g_wouthl [128  * 2048];
__device__ float g_bias[2048];                    // permuted bih+bhh
__device__ float g_h1[512];
__device__ float g_c1[512];
// sort scratch
__device__ int g_hist[HIST_SZ];
__device__ int g_cursor[HIST_SZ];
__device__ int g_cnt[HIST_SZ];
__device__ int g_order[O_NODES];
__device__ int g_pos[O_NODES];

// ---------------- helpers ------------------------------------------------------
__device__ __forceinline__ float sigm(float x) { return 1.f / (1.f + expf(-x)); }
__device__ __forceinline__ void hilo(float x, __nv_bfloat16& h, __nv_bfloat16& l) {
    h = __float2bfloat16(x);
    l = __float2bfloat16(x - __bfloat162float(h));
}

__device__ __forceinline__ void mma_bf16(float* d,
                                         unsigned a0, unsigned a1, unsigned a2, unsigned a3,
                                         unsigned b0, unsigned b1) {
    asm volatile(
        "mma.sync.aligned.m16n8k16.row.col.f32.bf16.bf16.f32 "
        "{%0,%1,%2,%3}, {%4,%5,%6,%7}, {%8,%9}, {%0,%1,%2,%3};\n"
        : "+f"(d[0]), "+f"(d[1]), "+f"(d[2]), "+f"(d[3])
        : "r"(a0), "r"(a1), "r"(a2), "r"(a3), "r"(b0), "r"(b1));
}
__device__ __forceinline__ void cpa16(unsigned sdst, const void* gsrc, int src_bytes) {
    asm volatile("cp.async.cg.shared.global [%0], [%1], 16, %2;\n"
                 :: "r"(sdst), "l"(gsrc), "r"(src_bytes) : "memory");
}
__device__ __forceinline__ void cpa_commit() {
    asm volatile("cp.async.commit_group;\n" ::: "memory");
}
template<int N>
__device__ __forceinline__ void cpa_wait() {
    asm volatile("cp.async.wait_group %0;\n" :: "n"(N) : "memory");
}

// ---------------- split-bf16 mma.sync GEMM -------------------------------------
// C = epi(A @ B^T), computed as Ahi.Bhi + Ahi.Blo + Alo.Bhi (K_eff = 3K).
// A,B: bf16 hilo arrays [rows][2K]. Block 128x128, 4 warps x (64x64),
// BK=64 bf16 per stage (128 B/row), 2-stage cp.async, scalar 32-bit frag LDS
// (pitch 72 bf16 -> word pattern (4r+c) mod 32, conflict-free).
// EPI: 0 fp32 C (+bias) | 1 relu -> hilo H1 (N=512) | 2 newt: relu -> split
//      {H1 cols<512 | fp32 out cols 512..639 | H2 cols>=640} | 3 bias -> hilo H1
//      | 4 fused LSTM gate epilogue (writes hilo hout)
#define PITCHB  72
#define ASTGB   (128 * PITCHB)          // bf16 per stage array
#define TG_SMEM (4 * ASTGB * 2)         // 73728 bytes

template<int EPI, bool BIAS>
__global__ void __launch_bounds__(128, 2)
bgemm(const __nv_bfloat16* __restrict__ A, int lda,
      const __nv_bfloat16* __restrict__ B, int K,
      const float* __restrict__ bias,
      float* __restrict__ C, int ldc,
      __nv_bfloat16* __restrict__ H1, __nv_bfloat16* __restrict__ H2,
      int M, const int* __restrict__ mdev,
      int t, int L, const int* __restrict__ nbr,
      __nv_bfloat16* __restrict__ hout)
{
    if (mdev) M = *mdev;
    const int m0 = blockIdx.y * 128;
    if (m0 >= M) return;
    const int n0 = blockIdx.x * 128;

    extern __shared__ __nv_bfloat16 smem[];
    const unsigned sbase = (unsigned)__cvta_generic_to_shared(smem);

    const int tid  = threadIdx.x;
    const int warp = tid >> 5, lane = tid & 31;
    const int r = lane >> 2, c = lane & 3;
    const int wm = (warp & 1) * 64;
    const int wn = (warp >> 1) * 64;

    float acc[4][8][4];
#pragma unroll
    for (int i = 0; i < 4; i++)
#pragma unroll
        for (int j = 0; j < 8; j++)
#pragma unroll
            for (int q = 0; q < 4; q++) acc[i][j][q] = 0.f;

    const int J = K >> 6;     // 64-bf16 slabs per phase
    const int S = 3 * J;

    auto load_slab = [&](int s, int stg) {
        int p = s / J, j = s - p * J;
        int aoff = ((p == 2) ? K : 0) + j * 64;
        int boff = ((p == 1) ? K : 0) + j * 64;
#pragma unroll
        for (int i = 0; i < 8; i++) {
            int q = tid + i * 128;
            int row = q >> 3, f8 = q & 7;
            unsigned soff = (unsigned)((stg * ASTGB + row * PITCHB + f8 * 8) * 2);
            const __nv_bfloat16* ga = A + (size_t)(m0 + row) * lda + aoff + f8 * 8;
            cpa16(sbase + soff, ga, ((m0 + row) < M) ? 16 : 0);
            const __nv_bfloat16* gb = B + (size_t)(n0 + row) * 2 * K + boff + f8 * 8;
            cpa16(sbase + (unsigned)(2 * ASTGB * 2) + soff, gb, 16);
        }
        cpa_commit();
    };

    load_slab(0, 0);

    for (int s = 0; s < S; ++s) {
        if (s + 1 < S) { load_slab(s + 1, (s + 1) & 1); cpa_wait<1>(); }
        else           { cpa_wait<0>(); }
        __syncthreads();

        const __nv_bfloat16* As = smem + (s & 1) * ASTGB;
        const __nv_bfloat16* Bs = smem + 2 * ASTGB + (s & 1) * ASTGB;
#pragma unroll
        for (int kk = 0; kk < 64; kk += 16) {
            unsigned ua[4][4], ub[8][2];
#pragma unroll
            for (int mt = 0; mt < 4; mt++) {
                int mb = wm + mt * 16 + r;
                ua[mt][0] = *(const unsigned*)&As[(mb    ) * PITCHB + kk + 2 * c    ];
                ua[mt][1] = *(const unsigned*)&As[(mb + 8) * PITCHB + kk + 2 * c    ];
                ua[mt][2] = *(const unsigned*)&As[(mb    ) * PITCHB + kk + 2 * c + 8];
                ua[mt][3] = *(const unsigned*)&As[(mb + 8) * PITCHB + kk + 2 * c + 8];
            }
#pragma unroll
            for (int nf = 0; nf < 8; nf++) {
                int nb = wn + nf * 8 + r;
                ub[nf][0] = *(const unsigned*)&Bs[nb * PITCHB + kk + 2 * c    ];
                ub[nf][1] = *(const unsigned*)&Bs[nb * PITCHB + kk + 2 * c + 8];
            }
#pragma unroll
            for (int mt = 0; mt < 4; mt++)
#pragma unroll
                for (int nf = 0; nf < 8; nf++)
                    mma_bf16(acc[mt][nf],
                             ua[mt][0], ua[mt][1], ua[mt][2], ua[mt][3],
                             ub[nf][0], ub[nf][1]);
        }
        __syncthreads();
    }

    if (EPI != 4) {
        const int cc2 = c * 2;
#pragma unroll
        for (int mt = 0; mt < 4; mt++) {
            int row0 = m0 + wm + mt * 16 + r;
#pragma unroll
            for (int nf = 0; nf < 8; nf++) {
                int col = n0 + wn + nf * 8 + cc2;
                float bx = 0.f, by = 0.f;
                if (BIAS) { bx = bias[col]; by = bias[col + 1]; }
#pragma unroll
                for (int h = 0; h < 2; h++) {
                    int row = row0 + h * 8;
                    if (row >= M) continue;
                    float vx = acc[mt][nf][h * 2 + 0] + bx;
                    float vy = acc[mt][nf][h * 2 + 1] + by;
                    if (EPI == 1 || EPI == 2) { vx = fmaxf(vx, 0.f); vy = fmaxf(vy, 0.f); }
                    if (EPI == 0) {
                        *(float2*)(C + (size_t)row * ldc + col) = make_float2(vx, vy);
                    } else if (EPI == 1 || EPI == 3) {
                        __nv_bfloat16 hx, lx, hy, ly;
                        hilo(vx, hx, lx); hilo(vy, hy, ly);
                        *(__nv_bfloat162*)(H1 + (size_t)row * 1024 + col) =
                            __nv_bfloat162(hx, hy);
                        *(__nv_bfloat162*)(H1 + (size_t)row * 1024 + 512 + col) =
                            __nv_bfloat162(lx, ly);
                    } else {  // EPI == 2: newt split
                        if (col < 512) {
                            __nv_bfloat16 hx, lx, hy, ly;
                            hilo(vx, hx, lx); hilo(vy, hy, ly);
                            *(__nv_bfloat162*)(H1 + (size_t)row * 1024 + col) =
                                __nv_bfloat162(hx, hy);
                            *(__nv_bfloat162*)(H1 + (size_t)row * 1024 + 512 + col) =
                                __nv_bfloat162(lx, ly);
                        } else if (col < 640) {
                            *(float2*)(C + (size_t)row * 128 + (col - 512)) =
                                make_float2(vx, vy);
                        } else {
                            __nv_bfloat16 hx, lx, hy, ly;
                            hilo(vx, hx, lx); hilo(vy, hy, ly);
                            *(__nv_bfloat162*)(H2 + (size_t)row * 1024 + (col - 640)) =
                                __nv_bfloat162(hx, hy);
                            *(__nv_bfloat162*)(H2 + (size_t)row * 1024 + 512 + (col - 640)) =
                                __nv_bfloat162(lx, ly);
                        }
                    }
                }
            }
        }
    } else {
        // fused LSTM epilogue: stage 128x128 gate tile in smem, then pointwise.
        float* gbuf = (float*)smem;   // 128 x 132 floats = 67584 B <= 73728
        const int cc2 = c * 2;
#pragma unroll
        for (int mt = 0; mt < 4; mt++) {
            int lr0 = wm + mt * 16 + r;
#pragma unroll
            for (int nf = 0; nf < 8; nf++) {
                int col = wn + nf * 8 + cc2;
                gbuf[lr0 * 132 + col]           = acc[mt][nf][0];
                gbuf[lr0 * 132 + col + 1]       = acc[mt][nf][1];
                gbuf[(lr0 + 8) * 132 + col]     = acc[mt][nf][2];
                gbuf[(lr0 + 8) * 132 + col + 1] = acc[mt][nf][3];
            }
        }
        __syncthreads();
        const int jj0 = (tid & 3) * 8;
#pragma unroll
        for (int pass = 0; pass < 4; pass++) {
            int rl = pass * 32 + (tid >> 2);
            int row = m0 + rl;
            if (row < M) {
                int node = g_order[row];
                int idx  = nbr[(size_t)node * L + t];   // active rows => idx > 0
                const float* gx = (idx <= T_EDGES)
                    ? g_gxs + (size_t)(idx - 1) * NG
                    : g_gxo + (size_t)(idx - 1 - T_EDGES) * NG;
#pragma unroll
                for (int u = 0; u < 8; u++) {
                    int jj = jj0 + u;
                    float gi = gbuf[rl * 132 + jj]      + gx[n0 + jj]      + g_bias[n0 + jj];
                    float gf = gbuf[rl * 132 + 32 + jj] + gx[n0 + 32 + jj] + g_bias[n0 + 32 + jj];
                    float gg = gbuf[rl * 132 + 64 + jj] + gx[n0 + 64 + jj] + g_bias[n0 + 64 + jj];
                    float go = gbuf[rl * 132 + 96 + jj] + gx[n0 + 96 + jj] + g_bias[n0 + 96 + jj];
                    int j = (n0 >> 2) + jj;    // global hidden index
                    float cc = g_cs[(size_t)row * HH + j];
                    float c2 = sigm(gf) * cc + sigm(gi) * tanhf(gg);
                    float h2 = sigm(go) * tanhf(c2);
                    g_cs[(size_t)row * HH + j] = c2;
                    __nv_bfloat16 hh, hl;
                    hilo(h2, hh, hl);
                    hout[(size_t)row * 1024 + j]       = hh;
                    hout[(size_t)row * 1024 + 512 + j] = hl;
                }
            }
        }
    }
}

// ---------------- prep / pointwise kernels -------------------------------------
// src[r][c] (ld src_ld) -> dst[r][c]=hi, dst[r][Kc+c]=lo (ld 2*Kc)
__global__ void k_cvt(const float* __restrict__ src, int src_ld,
                      __nv_bfloat16* __restrict__ dst, int Kc, int total)
{
    int i = blockIdx.x * blockDim.x + threadIdx.x;
    if (i >= total) return;
    int r = i / Kc, c = i - r * Kc;
    __nv_bfloat16 h, l;
    hilo(src[(size_t)r * src_ld + c], h, l);
    dst[(size_t)r * 2 * Kc + c] = h;
    dst[(size_t)r * 2 * Kc + Kc + c] = l;
}

// gate-permuted rows of W[2048,512] -> hilo [2048][1024]
__global__ void k_perm_whl(const float* __restrict__ W, __nv_bfloat16* __restrict__ out)
{
    int i = blockIdx.x * blockDim.x + threadIdx.x;
    if (i >= 2048 * 512) return;
    int p = i >> 9, k = i & 511;
    int g = (p >> 5) & 3, tg = p >> 7, jj = p & 31;
    int orig = g * 512 + tg * 32 + jj;
    __nv_bfloat16 h, l;
    hilo(W[(size_t)orig * 512 + k], h, l);
    out[(size_t)p * 1024 + k] = h;
    out[(size_t)p * 1024 + 512 + k] = l;
}

__global__ void k_perm_bias(const float* __restrict__ bih, const float* __restrict__ bhh)
{
    int p = blockIdx.x * blockDim.x + threadIdx.x;
    if (p >= 2048) return;
    int g = (p >> 5) & 3, tg = p >> 7, jj = p & 31;
    int orig = g * 512 + tg * 32 + jj;
    g_bias[p] = bih[orig] + bhh[orig];
}

__global__ void k_zero_hist()
{
    int i = blockIdx.x * blockDim.x + threadIdx.x;
    if (i < HIST_SZ) g_hist[i] = 0;
}
__global__ void k_hist(const int* __restrict__ lengths)
{
    int n = blockIdx.x * blockDim.x + threadIdx.x;
    if (n < O_NODES) atomicAdd(&g_hist[lengths[n]], 1);
}
__global__ void k_scan(int L)
{
    int run = 0;
    for (int len = L; len >= 0; --len) {
        g_cursor[len] = run;
        g_cnt[len]    = run;
        run += g_hist[len];
    }
}
__global__ void k_scatter(const int* __restrict__ lengths)
{
    int n = blockIdx.x * blockDim.x + threadIdx.x;
    if (n >= O_NODES) return;
    int pos = atomicAdd(&g_cursor[lengths[n]], 1);
    g_order[pos] = n;
    g_pos[n] = pos;
}

__global__ void k_build_curhl(const float* __restrict__ obj,
                              const float* __restrict__ pred,
                              const int* __restrict__ edges)
{
    int i = blockIdx.x * blockDim.x + threadIdx.x;
    if (i >= T_EDGES * 384) return;
    int e = i / 384, q = i - e * 384;
    float v;
    if (q < 128)       v = obj[(size_t)edges[2 * e] * 128 + q];
    else if (q < 256)  v = pred[(size_t)e * 128 + (q - 128)];
    else               v = obj[(size_t)edges[2 * e + 1] * 128 + (q - 256)];
    __nv_bfloat16 h, l;
    hilo(v, h, l);
    g_curhl[(size_t)e * 768 + q] = h;
    g_curhl[(size_t)e * 768 + 384 + q] = l;
}

// step 0: x=0, h=0 -> gates = biases only; identical for all nodes
__global__ void k_step0a()
{
    int j = threadIdx.x;
    int tg = j >> 5, jj = j & 31;
    int base = tg * 128 + jj;
    float gi = g_bias[base];
    float gf = g_bias[base + 32];
    float gg = g_bias[base + 64];
    float go = g_bias[base + 96];
    float c1 = sigm(gi) * tanhf(gg);          // c0 = 0
    float h1 = sigm(go) * tanhf(c1);
    g_c1[j] = c1;
    g_h1[j] = h1;
}
// step 0 "writes" buffer B (read by step 1)
__global__ void k_step0b()
{
    int i = blockIdx.x * blockDim.x + threadIdx.x;
    if (i >= O_NODES * HH) return;
    int j = i & 511;
    g_cs[i] = g_c1[j];
    __nv_bfloat16 h, l;
    hilo(g_h1[j], h, l);
    g_hsB[(size_t)(i >> 9) * 1024 + j]       = h;
    g_hsB[(size_t)(i >> 9) * 1024 + 512 + j] = l;
}

// pchl[n] = hilo([ h(last buf, sorted pos) | prev ]) as [n][2048]
__global__ void k_build_pc(const int* __restrict__ lengths)
{
    int i = blockIdx.x * blockDim.x + threadIdx.x;
    if (i >= O_NODES * HH) return;
    int n = i >> 9, j = i & 511;
    const __nv_bfloat16* hb = (lengths[n] & 1) ? g_hsB : g_hsA;
    size_t hrow = (size_t)g_pos[n] * 1024;
    g_pchl[(size_t)n * 2048 + j]        = hb[hrow + j];
    g_pchl[(size_t)n * 2048 + 1024 + j] = hb[hrow + 512 + j];
    g_pchl[(size_t)n * 2048 + 512 + j]  = g_prevhl[(size_t)n * 1024 + j];
    g_pchl[(size_t)n * 2048 + 1536 + j] = g_prevhl[(size_t)n * 1024 + 512 + j];
}

// ---------------- launcher -----------------------------------------------------
extern "C" void kernel_launch(void* const* d_in, const int* in_sizes, int n_in,
                              void* d_out, int out_size)
{
    const float* obj    = (const float*)d_in[0];
    const float* pred   = (const float*)d_in[1];
    const int*   edges  = (const int*)  d_in[2];
    const int*   nbr    = (const int*)  d_in[3];
    const int*   lengths= (const int*)  d_in[4];
    const float* W1     = (const float*)d_in[5];
    const float* b1     = (const float*)d_in[6];
    const float* W2     = (const float*)d_in[7];
    const float* b2     = (const float*)d_in[8];
    const float* Wih    = (const float*)d_in[9];
    const float* Whh    = (const float*)d_in[10];
    const float* bih    = (const float*)d_in[11];
    const float* bhh    = (const float*)d_in[12];
    const float* Wproj  = (const float*)d_in[13];
    const float* bproj  = (const float*)d_in[14];
    const float* Wout   = (const float*)d_in[15];
    const float* bout   = (const float*)d_in[16];
    float* out = (float*)d_out;

    const int L = in_sizes[3] / O_NODES;

    __nv_bfloat16 *p_curhl, *p_midhl, *p_shl, *p_ohl, *p_objhl, *p_prevhl,
                  *p_hsA, *p_hsB, *p_pchl;
    __nv_bfloat16 *p_w1, *p_w2, *p_wih, *p_whh, *p_wproj, *p_wout;
    float *p_gxs, *p_gxo;
    int *p_cnt;
    cudaGetSymbolAddress((void**)&p_curhl, g_curhl);
    cudaGetSymbolAddress((void**)&p_midhl, g_midhl);
    cudaGetSymbolAddress((void**)&p_shl,   g_shl);
    cudaGetSymbolAddress((void**)&p_ohl,   g_ohl);
    cudaGetSymbolAddress((void**)&p_objhl, g_objhl);
    cudaGetSymbolAddress((void**)&p_prevhl,g_prevhl);
    cudaGetSymbolAddress((void**)&p_hsA,   g_hsA);
    cudaGetSymbolAddress((void**)&p_hsB,   g_hsB);
    cudaGetSymbolAddress((void**)&p_pchl,  g_pchl);
    cudaGetSymbolAddress((void**)&p_w1,    g_w1hl);
    cudaGetSymbolAddress((void**)&p_w2,    g_w2hl);
    cudaGetSymbolAddress((void**)&p_wih,   g_wihhl);
    cudaGetSymbolAddress((void**)&p_whh,   g_whhhl);
    cudaGetSymbolAddress((void**)&p_wproj, g_wprojhl);
    cudaGetSymbolAddress((void**)&p_wout,  g_wouthl);
    cudaGetSymbolAddress((void**)&p_gxs,   g_gxs);
    cudaGetSymbolAddress((void**)&p_gxo,   g_gxo);
    cudaGetSymbolAddress((void**)&p_cnt,   g_cnt);

    cudaFuncSetAttribute(bgemm<0, false>, cudaFuncAttributeMaxDynamicSharedMemorySize, TG_SMEM);
    cudaFuncSetAttribute(bgemm<0, true >, cudaFuncAttributeMaxDynamicSharedMemorySize, TG_SMEM);
    cudaFuncSetAttribute(bgemm<1, true >, cudaFuncAttributeMaxDynamicSharedMemorySize, TG_SMEM);
    cudaFuncSetAttribute(bgemm<2, true >, cudaFuncAttributeMaxDynamicSharedMemorySize, TG_SMEM);
    cudaFuncSetAttribute(bgemm<3, true >, cudaFuncAttributeMaxDynamicSharedMemorySize, TG_SMEM);
    cudaFuncSetAttribute(bgemm<4, false>, cudaFuncAttributeMaxDynamicSharedMemorySize, TG_SMEM);

    const int MT_E = (T_EDGES + 127) / 128;   // 391
    const int MT_O = (O_NODES + 127) / 128;   // 79

    // weight prep (fp32 -> bf16 hilo; Wih/Whh gate-permuted)
    k_cvt<<<(512 * 384 + 255) / 256, 256>>>(W1, 384, p_w1, 384, 512 * 384);
    k_cvt<<<(1152 * 512 + 255) / 256, 256>>>(W2, 512, p_w2, 512, 1152 * 512);
    k_perm_whl<<<(2048 * 512 + 255) / 256, 256>>>(Wih, p_wih);
    k_perm_whl<<<(2048 * 512 + 255) / 256, 256>>>(Whh, p_whh);
    k_cvt<<<(512 * 128 + 255) / 256, 256>>>(Wproj, 128, p_wproj, 128, 512 * 128);
    k_cvt<<<(128 * 1024 + 255) / 256, 256>>>(Wout, 1024, p_wout, 1024, 128 * 1024);
    k_cvt<<<(O_NODES * 128 + 255) / 256, 256>>>(obj, 128, p_objhl, 128, O_NODES * 128);
    k_perm_bias<<<8, 256>>>(bih, bhh);

    // node sort by length (descending)
    k_zero_hist<<<HIST_SZ / 256, 256>>>();
    k_hist<<<(O_NODES + 255) / 256, 256>>>(lengths);
    k_scan<<<1, 1>>>(L);
    k_scatter<<<(O_NODES + 255) / 256, 256>>>(lengths);

    // edge MLP (mid -> hilo fused; newt split: shl | new_p->out | ohl)
    k_build_curhl<<<(T_EDGES * 384 + 255) / 256, 256>>>(obj, pred, edges);
    bgemm<1, true ><<<dim3(4, MT_E), 128, TG_SMEM>>>(p_curhl, 768, p_w1, 384, b1,
        nullptr, 0, p_midhl, nullptr, T_EDGES, nullptr, 0, 0, nullptr, nullptr);
    bgemm<2, true ><<<dim3(9, MT_E), 128, TG_SMEM>>>(p_midhl, 1024, p_w2, 512, b2,
        out + (size_t)O_NODES * 128, 128, p_shl, p_ohl, T_EDGES, nullptr, 0, 0, nullptr, nullptr);

    // LSTM input-gate precompute (permuted gate columns)
    bgemm<0, false><<<dim3(16, MT_E), 128, TG_SMEM>>>(p_shl, 1024, p_wih, 512, nullptr,
        p_gxs, NG, nullptr, nullptr, T_EDGES, nullptr, 0, 0, nullptr, nullptr);
    bgemm<0, false><<<dim3(16, MT_E), 128, TG_SMEM>>>(p_ohl, 1024, p_wih, 512, nullptr,
        p_gxo, NG, nullptr, nullptr, T_EDGES, nullptr, 0, 0, nullptr, nullptr);

    // prev = obj @ Wproj^T + bproj (hilo output)
    bgemm<3, true ><<<dim3(4, MT_O), 128, TG_SMEM>>>(p_objhl, 256, p_wproj, 128, bproj,
        nullptr, 0, p_prevhl, nullptr, O_NODES, nullptr, 0, 0, nullptr, nullptr);

    // LSTM step 0 closed form (buffer B), then fused steps t=1..L-1 (ping-pong)
    k_step0a<<<1, 512>>>();
    k_step0b<<<(O_NODES * HH + 255) / 256, 256>>>();
    for (int t = 1; t < L; ++t) {
        __nv_bfloat16* hin  = (t & 1) ? p_hsB : p_hsA;
        __nv_bfloat16* hout = (t & 1) ? p_hsA : p_hsB;
        bgemm<4, false><<<dim3(16, MT_O), 128, TG_SMEM>>>(hin, 1024, p_whh, 512, nullptr,
            nullptr, 0, nullptr, nullptr, O_NODES, p_cnt + t, t, L, nbr, hout);
    }

    // new_obj = [pooled | prev] @ Wout^T + bout (exact fp32 epilogue)
    k_build_pc<<<(O_NODES * HH + 255) / 256, 256>>>(lengths);
    bgemm<0, true ><<<dim3(1, MT_O), 128, TG_SMEM>>>(p_pchl, 2048, p_wout, 1024, bout,
        out, 128, nullptr, nullptr, O_NODES, nullptr, 0, 0, nullptr, nullptr);
}

// round 12
// speedup vs baseline: 1.4641x; 1.4641x over previous
#include <cuda_runtime.h>
#include <cstdint>
#include <math.h>

// Problem constants
#define O_NODES 10000
#define T_EDGES 50000
#define HH      512
#define NG      2048
#define HIST_SZ 131072

// ---------------- scratch (__device__ globals) --------------------------------
__device__ float g_cur [(size_t)T_EDGES * 384];
__device__ float g_mid [(size_t)T_EDGES * HH];
__device__ float g_x32 [(size_t)(2 * T_EDGES) * HH];   // [new_s rows | new_o rows]
__device__ float g_gx  [(size_t)(2 * T_EDGES) * NG];   // unified input gates
__device__ float g_hsA [(size_t)O_NODES * HH];         // h ping-pong buffer 0
__device__ float g_hsB [(size_t)O_NODES * HH];         // h ping-pong buffer 1
__device__ float g_cs  [(size_t)O_NODES * HH];         // full fp32 c state
__device__ float g_pc  [(size_t)O_NODES * 1024];       // [pooled | prev]
__device__ float g_obj32[(size_t)O_NODES * 128];
// tf32-rounded weights (Wih/Whh rows gate-permuted)
__device__ float g_w1r   [512  * 384];
__device__ float g_w2r   [1152 * 512];
__device__ float g_wihr  [2048 * 512];
__device__ float g_whhr  [2048 * 512];
__device__ float g_wprojr[512  * 128];
__device__ float g_woutr [128  * 1024];
__device__ float g_bias  [2048];                  // permuted bih+bhh
__device__ float g_h1[512];
__device__ float g_c1[512];
__device__ float g_ghh1[2048];                    // h1 @ Whh^T (permuted cols)
// sort scratch
__device__ int g_hist[HIST_SZ];
__device__ int g_cursor[HIST_SZ];
__device__ int g_cnt[HIST_SZ];
__device__ int g_order[O_NODES];
__device__ int g_pos[O_NODES];

// ---------------- helpers ------------------------------------------------------
__device__ __forceinline__ float roundtf(float x) {
    unsigned u;
    asm("cvt.rna.tf32.f32 %0, %1;" : "=r"(u) : "f"(x));
    return __uint_as_float(u);
}
__device__ __forceinline__ float sigm(float x) { return 1.f / (1.f + expf(-x)); }

__device__ __forceinline__ void mma_tf32(float* d, const unsigned* a, const unsigned* b) {
    asm volatile(
        "mma.sync.aligned.m16n8k8.row.col.f32.tf32.tf32.f32 "
        "{%0,%1,%2,%3}, {%4,%5,%6,%7}, {%8,%9}, {%0,%1,%2,%3};\n"
        : "+f"(d[0]), "+f"(d[1]), "+f"(d[2]), "+f"(d[3])
        : "r"(a[0]), "r"(a[1]), "r"(a[2]), "r"(a[3]), "r"(b[0]), "r"(b[1]));
}
__device__ __forceinline__ void cpa16(unsigned sdst, const float* gsrc, int src_bytes) {
    asm volatile("cp.async.cg.shared.global [%0], [%1], 16, %2;\n"
                 :: "r"(sdst), "l"(gsrc), "r"(src_bytes) : "memory");
}
__device__ __forceinline__ void cpa_commit() {
    asm volatile("cp.async.commit_group;\n" ::: "memory");
}
template<int N>
__device__ __forceinline__ void cpa_wait() {
    asm volatile("cp.async.wait_group %0;\n" :: "n"(N) : "memory");
}

// ---------------- tf32 tensor-core GEMM ----------------------------------------
// C[M,N] = epi(A[M,K] @ B[N,K]^T). Inputs pre-rounded to tf32.
// Block 128x128, 4 warps x (64x64), BK=32 per stage, 2-stage cp.async.
// EPI: 0 exact(+bias) | 1 relu+round(+bias) | 2 newt-split: relu; cols<512 ->
//      round->X rows; [512,640) -> fp32 C (new_p); >=640 -> round->X rows+T_EDGES
//      | 3 round(+bias) | 4 fused LSTM gate epilogue (writes hout, not C)
#define PITCH   36
#define ASTG    (128 * PITCH)          // floats per A stage
#define TG_SMEM (4 * ASTG * 4)         // bytes: 2 stages x (A+B)

template<int EPI, bool BIAS>
__global__ void __launch_bounds__(128, 2)
tgemm(const float* __restrict__ A, int lda,
      const float* __restrict__ B, int K,
      const float* __restrict__ bias,
      float* __restrict__ C, int ldc,
      float* __restrict__ X,
      int M, const int* __restrict__ mdev,
      int t, int L, const int* __restrict__ nbr,
      float* __restrict__ hout)
{
    if (mdev) M = *mdev;
    const int m0 = blockIdx.y * 128;
    if (m0 >= M) return;
    const int n0 = blockIdx.x * 128;

    extern __shared__ float smem[];
    const unsigned sbase = (unsigned)__cvta_generic_to_shared(smem);

    const int tid  = threadIdx.x;
    const int warp = tid >> 5, lane = tid & 31;
    const int r = lane >> 2, c = lane & 3;
    const int wm = (warp & 1) * 64;
    const int wn = (warp >> 1) * 64;

    float acc[4][8][4];
#pragma unroll
    for (int i = 0; i < 4; i++)
#pragma unroll
        for (int j = 0; j < 8; j++)
#pragma unroll
            for (int q = 0; q < 4; q++) acc[i][j][q] = 0.f;

    const int nk = K >> 5;

    auto load_stage = [&](int it, int stg) {
        int k0 = it << 5;
#pragma unroll
        for (int i = 0; i < 8; i++) {
            int q = tid + i * 128;
            int row = q >> 3, f4 = q & 7;
            unsigned soff = (unsigned)((stg * ASTG + row * PITCH + f4 * 4) * 4);
            const float* ga = A + (size_t)(m0 + row) * lda + k0 + f4 * 4;
            cpa16(sbase + soff, ga, ((m0 + row) < M) ? 16 : 0);
            const float* gb = B + (size_t)(n0 + row) * K + k0 + f4 * 4;
            cpa16(sbase + (unsigned)(2 * ASTG * 4) + soff, gb, 16);
        }
        cpa_commit();
    };

    load_stage(0, 0);

    for (int it = 0; it < nk; ++it) {
        if (it + 1 < nk) { load_stage(it + 1, (it + 1) & 1); cpa_wait<1>(); }
        else             { cpa_wait<0>(); }
        __syncthreads();

        const float* As = smem + (it & 1) * ASTG;
        const float* Bs = smem + 2 * ASTG + (it & 1) * ASTG;
#pragma unroll
        for (int kk = 0; kk < 32; kk += 8) {
            unsigned ua[4][4], ub[8][2];
#pragma unroll
            for (int mt = 0; mt < 4; mt++) {
                int mb = wm + mt * 16 + r;
                ua[mt][0] = __float_as_uint(As[(mb    ) * PITCH + kk + c    ]);
                ua[mt][1] = __float_as_uint(As[(mb + 8) * PITCH + kk + c    ]);
                ua[mt][2] = __float_as_uint(As[(mb    ) * PITCH + kk + c + 4]);
                ua[mt][3] = __float_as_uint(As[(mb + 8) * PITCH + kk + c + 4]);
            }
#pragma unroll
            for (int nf = 0; nf < 8; nf++) {
                int nb = wn + nf * 8 + r;
                ub[nf][0] = __float_as_uint(Bs[nb * PITCH + kk + c    ]);
                ub[nf][1] = __float_as_uint(Bs[nb * PITCH + kk + c + 4]);
            }
#pragma unroll
            for (int mt = 0; mt < 4; mt++)
#pragma unroll
                for (int nf = 0; nf < 8; nf++)
                    mma_tf32(acc[mt][nf], ua[mt], ub[nf]);
        }
        __syncthreads();
    }

    if (EPI != 4) {
        const int cc2 = c * 2;
#pragma unroll
        for (int mt = 0; mt < 4; mt++) {
            int row0 = m0 + wm + mt * 16 + r;
#pragma unroll
            for (int nf = 0; nf < 8; nf++) {
                int col = n0 + wn + nf * 8 + cc2;
                float bx = 0.f, by = 0.f;
                if (BIAS) { bx = bias[col]; by = bias[col + 1]; }
#pragma unroll
                for (int h = 0; h < 2; h++) {
                    int row = row0 + h * 8;
                    if (row >= M) continue;
                    float vx = acc[mt][nf][h * 2 + 0] + bx;
                    float vy = acc[mt][nf][h * 2 + 1] + by;
                    if (EPI == 1 || EPI == 2) { vx = fmaxf(vx, 0.f); vy = fmaxf(vy, 0.f); }
                    if (EPI == 1 || EPI == 3) { vx = roundtf(vx); vy = roundtf(vy); }
                    if (EPI == 2) {
                        if (col < 512) {
                            *(float2*)(X + (size_t)row * HH + col) =
                                make_float2(roundtf(vx), roundtf(vy));
                        } else if (col < 640) {
                            *(float2*)(C + (size_t)row * 128 + (col - 512)) =
                                make_float2(vx, vy);
                        } else {
                            *(float2*)(X + (size_t)(row + T_EDGES) * HH + (col - 640)) =
                                make_float2(roundtf(vx), roundtf(vy));
                        }
                    } else {
                        *(float2*)(C + (size_t)row * ldc + col) = make_float2(vx, vy);
                    }
                }
            }
        }
    } else {
        // fused LSTM epilogue: stage full 128x128 gate tile in smem, then pointwise.
        float* gbuf = smem;   // 128 x 132 floats = 67584 <= 73728
        const int cc2 = c * 2;
#pragma unroll
        for (int mt = 0; mt < 4; mt++) {
            int lr0 = wm + mt * 16 + r;
#pragma unroll
            for (int nf = 0; nf < 8; nf++) {
                int col = wn + nf * 8 + cc2;
                gbuf[lr0 * 132 + col]           = acc[mt][nf][0];
                gbuf[lr0 * 132 + col + 1]       = acc[mt][nf][1];
                gbuf[(lr0 + 8) * 132 + col]     = acc[mt][nf][2];
                gbuf[(lr0 + 8) * 132 + col + 1] = acc[mt][nf][3];
            }
        }
        __syncthreads();
        const int jj0 = (tid & 3) * 8;
#pragma unroll
        for (int pass = 0; pass < 4; pass++) {
            int rl = pass * 32 + (tid >> 2);
            int row = m0 + rl;
            if (row < M) {
                int node = g_order[row];
                int idx  = nbr[(size_t)node * L + t];   // active rows => idx > 0
                const float* gx = g_gx + (size_t)(idx - 1) * NG;
#pragma unroll
                for (int u = 0; u < 8; u++) {
                    int jj = jj0 + u;
                    float gi = gbuf[rl * 132 + jj]      + gx[n0 + jj]      + g_bias[n0 + jj];
                    float gf = gbuf[rl * 132 + 32 + jj] + gx[n0 + 32 + jj] + g_bias[n0 + 32 + jj];
                    float gg = gbuf[rl * 132 + 64 + jj] + gx[n0 + 64 + jj] + g_bias[n0 + 64 + jj];
                    float go = gbuf[rl * 132 + 96 + jj] + gx[n0 + 96 + jj] + g_bias[n0 + 96 + jj];
                    int j = (n0 >> 2) + jj;    // global hidden index
                    float cc = g_cs[(size_t)row * HH + j];
                    float c2 = sigm(gf) * cc + sigm(gi) * tanhf(gg);
                    float h2 = sigm(go) * tanhf(c2);
                    g_cs[(size_t)row * HH + j] = c2;
                    hout[(size_t)row * HH + j] = roundtf(h2);
                }
            }
        }
    }
}

// ---------------- prep / pointwise kernels -------------------------------------
// merged weight prep: ranges over one flat index space
#define PRE_W1    0
#define PRE_W2    (PRE_W1 + 512 * 384)          // 196608
#define PRE_WIH   (PRE_W2 + 1152 * 512)         // 786432
#define PRE_WHH   (PRE_WIH + 2048 * 512)        // 1835008
#define PRE_WPROJ (PRE_WHH + 2048 * 512)        // 2883584
#define PRE_WOUT  (PRE_WPROJ + 512 * 128)       // 2949120
#define PRE_OBJ   (PRE_WOUT + 128 * 1024)       // 3080192
#define PRE_BIAS  (PRE_OBJ + O_NODES * 128)     // 4360192
#define PRE_TOTAL (PRE_BIAS + 2048)             // 4362240

__global__ void k_prep(const float* __restrict__ W1, const float* __restrict__ W2,
                       const float* __restrict__ Wih, const float* __restrict__ Whh,
                       const float* __restrict__ Wproj, const float* __restrict__ Wout,
                       const float* __restrict__ obj,
                       const float* __restrict__ bih, const float* __restrict__ bhh)
{
    int i = blockIdx.x * blockDim.x + threadIdx.x;
    if (i >= PRE_TOTAL) return;
    if (i < PRE_W2) {
        g_w1r[i] = roundtf(W1[i]);
    } else if (i < PRE_WIH) {
        int q = i - PRE_W2;  g_w2r[q] = roundtf(W2[q]);
    } else if (i < PRE_WPROJ) {
        int q = (i < PRE_WHH) ? (i - PRE_WIH) : (i - PRE_WHH);
        const float* W = (i < PRE_WHH) ? Wih : Whh;
        float* out = (i < PRE_WHH) ? g_wihr : g_whhr;
        int p = q >> 9, k = q & 511;
        int g = (p >> 5) & 3, tg = p >> 7, jj = p & 31;
        int orig = g * 512 + tg * 32 + jj;
        out[q] = roundtf(W[(size_t)orig * 512 + k]);
    } else if (i < PRE_WOUT) {
        int q = i - PRE_WPROJ;  g_wprojr[q] = roundtf(Wproj[q]);
    } else if (i < PRE_OBJ) {
        int q = i - PRE_WOUT;  g_woutr[q] = roundtf(Wout[q]);
    } else if (i < PRE_BIAS) {
        int q = i - PRE_OBJ;  g_obj32[q] = roundtf(obj[q]);
    } else {
        int p = i - PRE_BIAS;
        int g = (p >> 5) & 3, tg = p >> 7, jj = p & 31;
        int orig = g * 512 + tg * 32 + jj;
        g_bias[p] = bih[orig] + bhh[orig];
    }
}

__global__ void k_zero_hist()
{
    int i = blockIdx.x * blockDim.x + threadIdx.x;
    if (i < HIST_SZ) g_hist[i] = 0;
}
__global__ void k_hist(const int* __restrict__ lengths)
{
    int n = blockIdx.x * blockDim.x + threadIdx.x;
    if (n < O_NODES) atomicAdd(&g_hist[lengths[n]], 1);
}
__global__ void k_scan(int L)
{
    int run = 0;
    for (int len = L; len >= 0; --len) {
        g_cursor[len] = run;
        g_cnt[len]    = run;
        run += g_hist[len];
    }
}
__global__ void k_scatter(const int* __restrict__ lengths)
{
    int n = blockIdx.x * blockDim.x + threadIdx.x;
    if (n >= O_NODES) return;
    int pos = atomicAdd(&g_cursor[lengths[n]], 1);
    g_order[pos] = n;
    g_pos[n] = pos;
}

__global__ void k_build_cur(const float* __restrict__ obj,
                            const float* __restrict__ pred,
                            const int* __restrict__ edges)
{
    int i = blockIdx.x * blockDim.x + threadIdx.x;
    if (i >= T_EDGES * 384) return;
    int e = i / 384, q = i - e * 384;
    float v;
    if (q < 128)       v = obj[(size_t)edges[2 * e] * 128 + q];
    else if (q < 256)  v = pred[(size_t)e * 128 + (q - 128)];
    else               v = obj[(size_t)edges[2 * e + 1] * 128 + (q - 256)];
    g_cur[(size_t)e * 384 + q] = roundtf(v);
}

// step 0: x=0, h=0 -> gates = biases only; identical for all nodes
__global__ void k_step0a()
{
    int j = threadIdx.x;
    int tg = j >> 5, jj = j & 31;
    int base = tg * 128 + jj;
    float gi = g_bias[base];
    float gf = g_bias[base + 32];
    float gg = g_bias[base + 64];
    float go = g_bias[base + 96];
    float c1 = sigm(gi) * tanhf(gg);          // c0 = 0
    float h1 = sigm(go) * tanhf(c1);
    g_c1[j] = c1;
    g_h1[j] = roundtf(h1);
}
// step 0 "writes" buffer B (read conceptually by step 1)
__global__ void k_step0b()
{
    int i = blockIdx.x * blockDim.x + threadIdx.x;
    if (i >= O_NODES * HH) return;
    g_cs[i]  = g_c1[i & 511];
    g_hsB[i] = g_h1[i & 511];
}

// ghh1[p] = sum_k h1[k] * Whh_perm[p][k]  (h1 identical across nodes)
__global__ void k_ghh1()
{
    int p = blockIdx.x * blockDim.x + threadIdx.x;
    if (p >= 2048) return;
    const float* w = g_whhr + (size_t)p * 512;
    float s = 0.f;
    for (int k = 0; k < 512; ++k) s = fmaf(g_h1[k], w[k], s);
    g_ghh1[p] = s;
}

// step 1 pointwise: gates = ghh1 + gx + bias (h-GEMM replaced by broadcast).
// Writes buffer A (= hbuf[(1+1)&1]).
__global__ void k_step1(int L, const int* __restrict__ nbr)
{
    int row = blockIdx.x;
    if (row >= g_cnt[1]) return;
    int j = threadIdx.x;
    int node = g_order[row];
    int idx  = nbr[(size_t)node * L + 1];
    const float* gx = g_gx + (size_t)(idx - 1) * NG;
    int tg = j >> 5, jj = j & 31;
    int base = tg * 128 + jj;
    float gi = g_ghh1[base]      + gx[base]      + g_bias[base];
    float gf = g_ghh1[base + 32] + gx[base + 32] + g_bias[base + 32];
    float gg = g_ghh1[base + 64] + gx[base + 64] + g_bias[base + 64];
    float go = g_ghh1[base + 96] + gx[base + 96] + g_bias[base + 96];
    float cc = g_cs[(size_t)row * HH + j];
    float c2 = sigm(gf) * cc + sigm(gi) * tanhf(gg);
    float h2 = sigm(go) * tanhf(c2);
    g_cs[(size_t)row * HH + j] = c2;
    g_hsA[(size_t)row * HH + j] = roundtf(h2);
}

// pooled half of pc: pc[n][0..127 f4] = hbuf[lengths[n]&1][pos[n]]
__global__ void k_build_pc_h(const int* __restrict__ lengths)
{
    int i = blockIdx.x * blockDim.x + threadIdx.x;
    if (i >= O_NODES * 128) return;
    int n = i >> 7, q = i & 127;
    const float* hb = (lengths[n] & 1) ? g_hsB : g_hsA;
    ((float4*)g_pc)[(size_t)n * 256 + q] =
        ((const float4*)hb)[(size_t)g_pos[n] * 128 + q];
}

// ---------------- launcher -----------------------------------------------------
extern "C" void kernel_launch(void* const* d_in, const int* in_sizes, int n_in,
                              void* d_out, int out_size)
{
    const float* obj    = (const float*)d_in[0];
    const float* pred   = (const float*)d_in[1];
    const int*   edges  = (const int*)  d_in[2];
    const int*   nbr    = (const int*)  d_in[3];
    const int*   lengths= (const int*)  d_in[4];
    const float* W1     = (const float*)d_in[5];
    const float* b1     = (const float*)d_in[6];
    const float* W2     = (const float*)d_in[7];
    const float* b2     = (const float*)d_in[8];
    const float* Wih    = (const float*)d_in[9];
    const float* Whh    = (const float*)d_in[10];
    const float* bih    = (const float*)d_in[11];
    const float* bhh    = (const float*)d_in[12];
    const float* Wproj  = (const float*)d_in[13];
    const float* bproj  = (const float*)d_in[14];
    const float* Wout   = (const float*)d_in[15];
    const float* bout   = (const float*)d_in[16];
    float* out = (float*)d_out;

    const int L = in_sizes[3] / O_NODES;

    float *p_cur, *p_mid, *p_x32, *p_gx, *p_hsA, *p_hsB, *p_pc, *p_obj32;
    float *p_w1, *p_w2, *p_wih, *p_whh, *p_wproj, *p_wout;
    int *p_cnt;
    cudaGetSymbolAddress((void**)&p_cur,   g_cur);
    cudaGetSymbolAddress((void**)&p_mid,   g_mid);
    cudaGetSymbolAddress((void**)&p_x32,   g_x32);
    cudaGetSymbolAddress((void**)&p_gx,    g_gx);
    cudaGetSymbolAddress((void**)&p_hsA,   g_hsA);
    cudaGetSymbolAddress((void**)&p_hsB,   g_hsB);
    cudaGetSymbolAddress((void**)&p_pc,    g_pc);
    cudaGetSymbolAddress((void**)&p_obj32, g_obj32);
    cudaGetSymbolAddress((void**)&p_w1,    g_w1r);
    cudaGetSymbolAddress((void**)&p_w2,    g_w2r);
    cudaGetSymbolAddress((void**)&p_wih,   g_wihr);
    cudaGetSymbolAddress((void**)&p_whh,   g_whhr);
    cudaGetSymbolAddress((void**)&p_wproj, g_wprojr);
    cudaGetSymbolAddress((void**)&p_wout,  g_woutr);
    cudaGetSymbolAddress((void**)&p_cnt,   g_cnt);

    cudaFuncSetAttribute(tgemm<0, false>, cudaFuncAttributeMaxDynamicSharedMemorySize, TG_SMEM);
    cudaFuncSetAttribute(tgemm<0, true >, cudaFuncAttributeMaxDynamicSharedMemorySize, TG_SMEM);
    cudaFuncSetAttribute(tgemm<1, true >, cudaFuncAttributeMaxDynamicSharedMemorySize, TG_SMEM);
    cudaFuncSetAttribute(tgemm<2, true >, cudaFuncAttributeMaxDynamicSharedMemorySize, TG_SMEM);
    cudaFuncSetAttribute(tgemm<3, true >, cudaFuncAttributeMaxDynamicSharedMemorySize, TG_SMEM);
    cudaFuncSetAttribute(tgemm<4, false>, cudaFuncAttributeMaxDynamicSharedMemorySize, TG_SMEM);

    const int MT_E = (T_EDGES + 127) / 128;        // 391
    const int MT_X = (2 * T_EDGES + 127) / 128;    // 782
    const int MT_O = (O_NODES + 127) / 128;        // 79

    // prep (all weight rounding/permutation + obj round + bias) in one launch
    k_prep<<<(PRE_TOTAL + 255) / 256, 256>>>(W1, W2, Wih, Whh, Wproj, Wout, obj, bih, bhh);

    // node sort by length (descending)
    k_zero_hist<<<HIST_SZ / 256, 256>>>();
    k_hist<<<(O_NODES + 255) / 256, 256>>>(lengths);
    k_scan<<<1, 1>>>(L);
    k_scatter<<<(O_NODES + 255) / 256, 256>>>(lengths);

    // edge MLP; GEMM2 writes new_s/new_o (rounded) to g_x32 and new_p to out
    k_build_cur<<<(T_EDGES * 384 + 255) / 256, 256>>>(obj, pred, edges);
    tgemm<1, true ><<<dim3(4, MT_E), 128, TG_SMEM>>>(p_cur, 384, p_w1, 384, b1,
        p_mid, 512, nullptr, T_EDGES, nullptr, 0, 0, nullptr, nullptr);
    tgemm<2, true ><<<dim3(9, MT_E), 128, TG_SMEM>>>(p_mid, 512, p_w2, 512, b2,
        out + (size_t)O_NODES * 128, 128, p_x32, T_EDGES, nullptr, 0, 0, nullptr, nullptr);

    // unified LSTM input-gate precompute: g_gx = g_x32 @ Wih_perm^T (100000 rows)
    tgemm<0, false><<<dim3(16, MT_X), 128, TG_SMEM>>>(p_x32, 512, p_wih, 512, nullptr,
        p_gx, NG, nullptr, 2 * T_EDGES, nullptr, 0, 0, nullptr, nullptr);

    // prev = obj @ Wproj^T + bproj, written directly into pc cols [512,1024)
    tgemm<3, true ><<<dim3(4, MT_O), 128, TG_SMEM>>>(p_obj32, 128, p_wproj, 128, bproj,
        p_pc + 512, 1024, nullptr, O_NODES, nullptr, 0, 0, nullptr, nullptr);

    // LSTM: step 0 closed form (buffer B); step 1 via broadcast ghh1 (buffer A);
    // steps t=2..L-1 fused GEMM+pointwise, ping-pong.
    k_step0a<<<1, 512>>>();
    k_step0b<<<(O_NODES * HH + 255) / 256, 256>>>();
    k_ghh1<<<8, 256>>>();
    k_step1<<<O_NODES, 512>>>(L, nbr);
    for (int t = 2; t < L; ++t) {
        float* hin  = (t & 1) ? p_hsB : p_hsA;
        float* hout = (t & 1) ? p_hsA : p_hsB;
        tgemm<4, false><<<dim3(16, MT_O), 128, TG_SMEM>>>(hin, 512, p_whh, 512, nullptr,
            nullptr, 0, nullptr, O_NODES, p_cnt + t, t, L, nbr, hout);
    }

    // pooled half of pc, then new_obj = pc @ Wout^T + bout (exact epilogue)
    k_build_pc_h<<<(O_NODES * 128 + 255) / 256, 256>>>(lengths);
    tgemm<0, true ><<<dim3(1, MT_O), 128, TG_SMEM>>>(p_pc, 1024, p_wout, 1024, bout,
        out, 128, nullptr, O_NODES, nullptr, 0, 0, nullptr, nullptr);
}

// round 14
// speedup vs baseline: 1.5865x; 1.0836x over previous
#include <cuda_runtime.h>
#include <cstdint>
#include <math.h>

// Problem constants
#define O_NODES 10000
#define T_EDGES 50000
#define HH      512
#define NG      2048
#define HIST_SZ 131072

// ---------------- scratch (__device__ globals) --------------------------------
__device__ float g_cur [(size_t)T_EDGES * 384];
__device__ float g_mid [(size_t)T_EDGES * HH];
__device__ float g_x32 [(size_t)(2 * T_EDGES) * HH];   // [new_s rows | new_o rows]
__device__ float g_hsA [(size_t)O_NODES * HH];         // h ping-pong buffer 0
__device__ float g_hsB [(size_t)O_NODES * HH];         // h ping-pong buffer 1
__device__ float g_cs  [(size_t)O_NODES * HH];         // full fp32 c state
__device__ float g_pc  [(size_t)O_NODES * 1024];       // [pooled | prev]
__device__ float g_obj32[(size_t)O_NODES * 128];
// tf32-rounded weights
__device__ float g_w1r   [512  * 384];
__device__ float g_w2r   [1152 * 512];
__device__ float g_whx   [2048 * 1024];           // [Whh_perm | Wih_perm] rows
__device__ float g_wprojr[512  * 128];
__device__ float g_woutr [128  * 1024];
__device__ float g_bias  [2048];                  // permuted bih+bhh
__device__ float g_h1[512];
__device__ float g_c1[512];
__device__ float g_ghh1[2048];                    // h1 @ Whh^T (permuted cols)
// sort scratch
__device__ int g_hist[HIST_SZ];
__device__ int g_cursor[HIST_SZ];
__device__ int g_cnt[HIST_SZ];
__device__ int g_order[O_NODES];
__device__ int g_pos[O_NODES];

// ---------------- helpers ------------------------------------------------------
__device__ __forceinline__ float roundtf(float x) {
    unsigned u;
    asm("cvt.rna.tf32.f32 %0, %1;" : "=r"(u) : "f"(x));
    return __uint_as_float(u);
}
__device__ __forceinline__ float sigm(float x) { return 1.f / (1.f + expf(-x)); }

__device__ __forceinline__ void mma_tf32(float* d, const unsigned* a, const unsigned* b) {
    asm volatile(
        "mma.sync.aligned.m16n8k8.row.col.f32.tf32.tf32.f32 "
        "{%0,%1,%2,%3}, {%4,%5,%6,%7}, {%8,%9}, {%0,%1,%2,%3};\n"
        : "+f"(d[0]), "+f"(d[1]), "+f"(d[2]), "+f"(d[3])
        : "r"(a[0]), "r"(a[1]), "r"(a[2]), "r"(a[3]), "r"(b[0]), "r"(b[1]));
}
__device__ __forceinline__ void cpa16(unsigned sdst, const float* gsrc, int src_bytes) {
    asm volatile("cp.async.cg.shared.global [%0], [%1], 16, %2;\n"
                 :: "r"(sdst), "l"(gsrc), "r"(src_bytes) : "memory");
}
__device__ __forceinline__ void cpa_commit() {
    asm volatile("cp.async.commit_group;\n" ::: "memory");
}
template<int N>
__device__ __forceinline__ void cpa_wait() {
    asm volatile("cp.async.wait_group %0;\n" :: "n"(N) : "memory");
}

#define PITCH   36
#define ASTG    (128 * PITCH)          // floats per A stage
#define TG_SMEM (4 * ASTG * 4)         // bytes: 2 stages x (A+B)

// ---------------- tf32 tensor-core GEMM ----------------------------------------
// C[M,N] = epi(A[M,K] @ B[N,K]^T). Inputs pre-rounded to tf32.
// Block 128x128, 4 warps x (64x64), BK=32 per stage, 2-stage cp.async.
// EPI: 0 exact(+bias) | 1 relu+round(+bias) | 2 newt-split: relu; cols<512 ->
//      round->X rows; [512,640) -> fp32 C (new_p); >=640 -> round->X rows+T_EDGES
//      | 3 round(+bias)
template<int EPI, bool BIAS>
__global__ void __launch_bounds__(128, 2)
tgemm(const float* __restrict__ A, int lda,
      const float* __restrict__ B, int K,
      const float* __restrict__ bias,
      float* __restrict__ C, int ldc,
      float* __restrict__ X, int M)
{
    const int m0 = blockIdx.y * 128;
    if (m0 >= M) return;
    const int n0 = blockIdx.x * 128;

    extern __shared__ float smem[];
    const unsigned sbase = (unsigned)__cvta_generic_to_shared(smem);

    const int tid  = threadIdx.x;
    const int warp = tid >> 5, lane = tid & 31;
    const int r = lane >> 2, c = lane & 3;
    const int wm = (warp & 1) * 64;
    const int wn = (warp >> 1) * 64;

    float acc[4][8][4];
#pragma unroll
    for (int i = 0; i < 4; i++)
#pragma unroll
        for (int j = 0; j < 8; j++)
#pragma unroll
            for (int q = 0; q < 4; q++) acc[i][j][q] = 0.f;

    const int nk = K >> 5;

    auto load_stage = [&](int it, int stg) {
        int k0 = it << 5;
#pragma unroll
        for (int i = 0; i < 8; i++) {
            int q = tid + i * 128;
            int row = q >> 3, f4 = q & 7;
            unsigned soff = (unsigned)((stg * ASTG + row * PITCH + f4 * 4) * 4);
            const float* ga = A + (size_t)(m0 + row) * lda + k0 + f4 * 4;
            cpa16(sbase + soff, ga, ((m0 + row) < M) ? 16 : 0);
            const float* gb = B + (size_t)(n0 + row) * K + k0 + f4 * 4;
            cpa16(sbase + (unsigned)(2 * ASTG * 4) + soff, gb, 16);
        }
        cpa_commit();
    };

    load_stage(0, 0);

    for (int it = 0; it < nk; ++it) {
        if (it + 1 < nk) { load_stage(it + 1, (it + 1) & 1); cpa_wait<1>(); }
        else             { cpa_wait<0>(); }
        __syncthreads();

        const float* As = smem + (it & 1) * ASTG;
        const float* Bs = smem + 2 * ASTG + (it & 1) * ASTG;
#pragma unroll
        for (int kk = 0; kk < 32; kk += 8) {
            unsigned ua[4][4], ub[8][2];
#pragma unroll
            for (int mt = 0; mt < 4; mt++) {
                int mb = wm + mt * 16 + r;
                ua[mt][0] = __float_as_uint(As[(mb    ) * PITCH + kk + c    ]);
                ua[mt][1] = __float_as_uint(As[(mb + 8) * PITCH + kk + c    ]);
                ua[mt][2] = __float_as_uint(As[(mb    ) * PITCH + kk + c + 4]);
                ua[mt][3] = __float_as_uint(As[(mb + 8) * PITCH + kk + c + 4]);
            }
#pragma unroll
            for (int nf = 0; nf < 8; nf++) {
                int nb = wn + nf * 8 + r;
                ub[nf][0] = __float_as_uint(Bs[nb * PITCH + kk + c    ]);
                ub[nf][1] = __float_as_uint(Bs[nb * PITCH + kk + c + 4]);
            }
#pragma unroll
            for (int mt = 0; mt < 4; mt++)
#pragma unroll
                for (int nf = 0; nf < 8; nf++)
                    mma_tf32(acc[mt][nf], ua[mt], ub[nf]);
        }
        __syncthreads();
    }

    const int cc2 = c * 2;
#pragma unroll
    for (int mt = 0; mt < 4; mt++) {
        int row0 = m0 + wm + mt * 16 + r;
#pragma unroll
        for (int nf = 0; nf < 8; nf++) {
            int col = n0 + wn + nf * 8 + cc2;
            float bx = 0.f, by = 0.f;
            if (BIAS) { bx = bias[col]; by = bias[col + 1]; }
#pragma unroll
            for (int h = 0; h < 2; h++) {
                int row = row0 + h * 8;
                if (row >= M) continue;
                float vx = acc[mt][nf][h * 2 + 0] + bx;
                float vy = acc[mt][nf][h * 2 + 1] + by;
                if (EPI == 1 || EPI == 2) { vx = fmaxf(vx, 0.f); vy = fmaxf(vy, 0.f); }
                if (EPI == 1 || EPI == 3) { vx = roundtf(vx); vy = roundtf(vy); }
                if (EPI == 2) {
                    if (col < 512) {
                        *(float2*)(X + (size_t)row * HH + col) =
                            make_float2(roundtf(vx), roundtf(vy));
                    } else if (col < 640) {
                        *(float2*)(C + (size_t)row * 128 + (col - 512)) =
                            make_float2(vx, vy);
                    } else {
                        *(float2*)(X + (size_t)(row + T_EDGES) * HH + (col - 640)) =
                            make_float2(roundtf(vx), roundtf(vy));
                    }
                } else {
                    *(float2*)(C + (size_t)row * ldc + col) = make_float2(vx, vy);
                }
            }
        }
    }
}

// ---------------- fused LSTM step: gates = [h|x_gathered] @ [Whh|Wih]^T --------
// T1: step 1 — x-only GEMM (K=512, B=Wih half), ghh1 broadcast added in epilogue.
// else: K=1024; stages <512 read h from hin, >=512 read x row sidx[row].
template<bool T1>
__global__ void __launch_bounds__(128, 2)
lstm_step(const float* __restrict__ hin,
          int t, int L, const int* __restrict__ nbr,
          const int* __restrict__ mdev,
          float* __restrict__ hout)
{
    const int M = *mdev;
    const int m0 = blockIdx.y * 128;
    if (m0 >= M) return;
    const int n0 = blockIdx.x * 128;

    extern __shared__ float smem[];
    __shared__ int sidx[128];
    const unsigned sbase = (unsigned)__cvta_generic_to_shared(smem);

    const int tid  = threadIdx.x;
    const int warp = tid >> 5, lane = tid & 31;
    const int r = lane >> 2, c = lane & 3;
    const int wm = (warp & 1) * 64;
    const int wn = (warp >> 1) * 64;

    if (tid < 128) {
        int row = m0 + tid;
        int s = 0;
        if (row < M) s = nbr[(size_t)g_order[row] * L + t] - 1;  // active => >0
        sidx[tid] = s;
    }
    __syncthreads();

    const float* Bw = T1 ? (g_whx + 512) : g_whx;
    const int K = T1 ? 512 : 1024;
    const int nk = K >> 5;

    float acc[4][8][4];
#pragma unroll
    for (int i = 0; i < 4; i++)
#pragma unroll
        for (int j = 0; j < 8; j++)
#pragma unroll
            for (int q = 0; q < 4; q++) acc[i][j][q] = 0.f;

    auto load_stage = [&](int it, int stg) {
        int k0 = it << 5;
#pragma unroll
        for (int i = 0; i < 8; i++) {
            int q = tid + i * 128;
            int row = q >> 3, f4 = q & 7;
            unsigned soff = (unsigned)((stg * ASTG + row * PITCH + f4 * 4) * 4);
            const float* ga;
            if (T1)            ga = g_x32 + (size_t)sidx[row] * HH + k0 + f4 * 4;
            else if (k0 < 512) ga = hin + (size_t)(m0 + row) * HH + k0 + f4 * 4;
            else               ga = g_x32 + (size_t)sidx[row] * HH + (k0 - 512) + f4 * 4;
            cpa16(sbase + soff, ga, ((m0 + row) < M) ? 16 : 0);
            const float* gb = Bw + (size_t)(n0 + row) * 1024 + k0 + f4 * 4;
            cpa16(sbase + (unsigned)(2 * ASTG * 4) + soff, gb, 16);
        }
        cpa_commit();
    };

    load_stage(0, 0);

    for (int it = 0; it < nk; ++it) {
        if (it + 1 < nk) { load_stage(it + 1, (it + 1) & 1); cpa_wait<1>(); }
        else             { cpa_wait<0>(); }
        __syncthreads();

        const float* As = smem + (it & 1) * ASTG;
        const float* Bs = smem + 2 * ASTG + (it & 1) * ASTG;
#pragma unroll
        for (int kk = 0; kk < 32; kk += 8) {
            unsigned ua[4][4], ub[8][2];
#pragma unroll
            for (int mt = 0; mt < 4; mt++) {
                int mb = wm + mt * 16 + r;
                ua[mt][0] = __float_as_uint(As[(mb    ) * PITCH + kk + c    ]);
                ua[mt][1] = __float_as_uint(As[(mb + 8) * PITCH + kk + c    ]);
                ua[mt][2] = __float_as_uint(As[(mb    ) * PITCH + kk + c + 4]);
                ua[mt][3] = __float_as_uint(As[(mb + 8) * PITCH + kk + c + 4]);
            }
#pragma unroll
            for (int nf = 0; nf < 8; nf++) {
                int nb = wn + nf * 8 + r;
                ub[nf][0] = __float_as_uint(Bs[nb * PITCH + kk + c    ]);
                ub[nf][1] = __float_as_uint(Bs[nb * PITCH + kk + c + 4]);
            }
#pragma unroll
            for (int mt = 0; mt < 4; mt++)
#pragma unroll
                for (int nf = 0; nf < 8; nf++)
                    mma_tf32(acc[mt][nf], ua[mt], ub[nf]);
        }
        __syncthreads();
    }

    // stage 128x128 gate tile in smem (pipeline buffers dead), then pointwise
    float* gbuf = smem;   // 128 x 132 floats = 67584 <= 73728
    const int cc2 = c * 2;
#pragma unroll
    for (int mt = 0; mt < 4; mt++) {
        int lr0 = wm + mt * 16 + r;
#pragma unroll
        for (int nf = 0; nf < 8; nf++) {
            int col = wn + nf * 8 + cc2;
            gbuf[lr0 * 132 + col]           = acc[mt][nf][0];
            gbuf[lr0 * 132 + col + 1]       = acc[mt][nf][1];
            gbuf[(lr0 + 8) * 132 + col]     = acc[mt][nf][2];
            gbuf[(lr0 + 8) * 132 + col + 1] = acc[mt][nf][3];
        }
    }
    __syncthreads();
    const int jj0 = (tid & 3) * 8;
#pragma unroll
    for (int pass = 0; pass < 4; pass++) {
        int rl = pass * 32 + (tid >> 2);
        int row = m0 + rl;
        if (row < M) {
#pragma unroll
            for (int u = 0; u < 8; u++) {
                int jj = jj0 + u;
                float gi = gbuf[rl * 132 + jj]      + g_bias[n0 + jj];
                float gf = gbuf[rl * 132 + 32 + jj] + g_bias[n0 + 32 + jj];
                float gg = gbuf[rl * 132 + 64 + jj] + g_bias[n0 + 64 + jj];
                float go = gbuf[rl * 132 + 96 + jj] + g_bias[n0 + 96 + jj];
                if (T1) {
                    gi += g_ghh1[n0 + jj];
                    gf += g_ghh1[n0 + 32 + jj];
                    gg += g_ghh1[n0 + 64 + jj];
                    go += g_ghh1[n0 + 96 + jj];
                }
                int j = (n0 >> 2) + jj;    // global hidden index
                float cc = g_cs[(size_t)row * HH + j];
                float c2 = sigm(gf) * cc + sigm(gi) * tanhf(gg);
                float h2 = sigm(go) * tanhf(c2);
                g_cs[(size_t)row * HH + j] = c2;
                hout[(size_t)row * HH + j] = roundtf(h2);
            }
        }
    }
}

// ---------------- prep / pointwise kernels -------------------------------------
#define PRE_W1    0
#define PRE_W2    (PRE_W1 + 512 * 384)
#define PRE_WIH   (PRE_W2 + 1152 * 512)
#define PRE_WHH   (PRE_WIH + 2048 * 512)
#define PRE_WPROJ (PRE_WHH + 2048 * 512)
#define PRE_WOUT  (PRE_WPROJ + 512 * 128)
#define PRE_OBJ   (PRE_WOUT + 128 * 1024)
#define PRE_BIAS  (PRE_OBJ + O_NODES * 128)
#define PRE_TOTAL (PRE_BIAS + 2048)

__global__ void k_prep(const float* __restrict__ W1, const float* __restrict__ W2,
                       const float* __restrict__ Wih, const float* __restrict__ Whh,
                       const float* __restrict__ Wproj, const float* __restrict__ Wout,
                       const float* __restrict__ obj,
                       const float* __restrict__ bih, const float* __restrict__ bhh)
{
    int i = blockIdx.x * blockDim.x + threadIdx.x;
    if (i >= PRE_TOTAL) return;
    if (i < PRE_W2) {
        g_w1r[i] = roundtf(W1[i]);
    } else if (i < PRE_WIH) {
        int q = i - PRE_W2;  g_w2r[q] = roundtf(W2[q]);
    } else if (i < PRE_WPROJ) {
        int q = (i < PRE_WHH) ? (i - PRE_WIH) : (i - PRE_WHH);
        const float* W = (i < PRE_WHH) ? Wih : Whh;
        int half = (i < PRE_WHH) ? 512 : 0;    // Wih -> cols [512,1024), Whh -> [0,512)
        int p = q >> 9, k = q & 511;
        int g = (p >> 5) & 3, tg = p >> 7, jj = p & 31;
        int orig = g * 512 + tg * 32 + jj;
        g_whx[(size_t)p * 1024 + half + k] = roundtf(W[(size_t)orig * 512 + k]);
    } else if (i < PRE_WOUT) {
        int q = i - PRE_WPROJ;  g_wprojr[q] = roundtf(Wproj[q]);
    } else if (i < PRE_OBJ) {
        int q = i - PRE_WOUT;  g_woutr[q] = roundtf(Wout[q]);
    } else if (i < PRE_BIAS) {
        int q = i - PRE_OBJ;  g_obj32[q] = roundtf(obj[q]);
    } else {
        int p = i - PRE_BIAS;
        int g = (p >> 5) & 3, tg = p >> 7, jj = p & 31;
        int orig = g * 512 + tg * 32 + jj;
        g_bias[p] = bih[orig] + bhh[orig];
    }
}

__global__ void k_zero_hist()
{
    int i = blockIdx.x * blockDim.x + threadIdx.x;
    if (i < HIST_SZ) g_hist[i] = 0;
}
__global__ void k_hist(const int* __restrict__ lengths)
{
    int n = blockIdx.x * blockDim.x + threadIdx.x;
    if (n < O_NODES) atomicAdd(&g_hist[lengths[n]], 1);
}
__global__ void k_scan(int L)
{
    int run = 0;
    for (int len = L; len >= 0; --len) {
        g_cursor[len] = run;
        g_cnt[len]    = run;
        run += g_hist[len];
    }
}
__global__ void k_scatter(const int* __restrict__ lengths)
{
    int n = blockIdx.x * blockDim.x + threadIdx.x;
    if (n >= O_NODES) return;
    int pos = atomicAdd(&g_cursor[lengths[n]], 1);
    g_order[pos] = n;
    g_pos[n] = pos;
}

__global__ void k_build_cur(const float* __restrict__ obj,
                            const float* __restrict__ pred,
                            const int* __restrict__ edges)
{
    int i = blockIdx.x * blockDim.x + threadIdx.x;
    if (i >= T_EDGES * 384) return;
    int e = i / 384, q = i - e * 384;
    float v;
    if (q < 128)       v = obj[(size_t)edges[2 * e] * 128 + q];
    else if (q < 256)  v = pred[(size_t)e * 128 + (q - 128)];
    else               v = obj[(size_t)edges[2 * e + 1] * 128 + (q - 256)];
    g_cur[(size_t)e * 384 + q] = roundtf(v);
}

// step 0: x=0, h=0 -> gates = biases only; identical for all nodes
__global__ void k_step0a()
{
    int j = threadIdx.x;
    int tg = j >> 5, jj = j & 31;
    int base = tg * 128 + jj;
    float gi = g_bias[base];
    float gf = g_bias[base + 32];
    float gg = g_bias[base + 64];
    float go = g_bias[base + 96];
    float c1 = sigm(gi) * tanhf(gg);          // c0 = 0
    float h1 = sigm(go) * tanhf(c1);
    g_c1[j] = c1;
    g_h1[j] = roundtf(h1);
}
__global__ void k_step0b()
{
    int i = blockIdx.x * blockDim.x + threadIdx.x;
    if (i >= O_NODES * HH) return;
    g_cs[i]  = g_c1[i & 511];
    g_hsB[i] = g_h1[i & 511];
}

// ghh1[p] = sum_k h1[k] * Whh_perm[p][k]
__global__ void k_ghh1()
{
    int p = blockIdx.x * blockDim.x + threadIdx.x;
    if (p >= 2048) return;
    const float* w = g_whx + (size_t)p * 1024;
    float s = 0.f;
    for (int k = 0; k < 512; ++k) s = fmaf(g_h1[k], w[k], s);
    g_ghh1[p] = s;
}

// pooled half of pc: pc[n][0..127 f4] = hbuf[lengths[n]&1][pos[n]]
__global__ void k_build_pc_h(const int* __restrict__ lengths)
{
    int i = blockIdx.x * blockDim.x + threadIdx.x;
    if (i >= O_NODES * 128) return;
    int n = i >> 7, q = i & 127;
    const float* hb = (lengths[n] & 1) ? g_hsB : g_hsA;
    ((float4*)g_pc)[(size_t)n * 256 + q] =
        ((const float4*)hb)[(size_t)g_pos[n] * 128 + q];
}

// ---------------- launcher -----------------------------------------------------
extern "C" void kernel_launch(void* const* d_in, const int* in_sizes, int n_in,
                              void* d_out, int out_size)
{
    const float* obj    = (const float*)d_in[0];
    const float* pred   = (const float*)d_in[1];
    const int*   edges  = (const int*)  d_in[2];
    const int*   nbr    = (const int*)  d_in[3];
    const int*   lengths= (const int*)  d_in[4];
    const float* W1     = (const float*)d_in[5];
    const float* b1     = (const float*)d_in[6];
    const float* W2     = (const float*)d_in[7];
    const float* b2     = (const float*)d_in[8];
    const float* Wih    = (const float*)d_in[9];
    const float* Whh    = (const float*)d_in[10];
    const float* bih    = (const float*)d_in[11];
    const float* bhh    = (const float*)d_in[12];
    const float* Wproj  = (const float*)d_in[13];
    const float* bproj  = (const float*)d_in[14];
    const float* Wout   = (const float*)d_in[15];
    const float* bout   = (const float*)d_in[16];
    float* out = (float*)d_out;

    const int L = in_sizes[3] / O_NODES;

    float *p_cur, *p_mid, *p_x32, *p_hsA, *p_hsB, *p_pc, *p_obj32;
    float *p_w1, *p_w2, *p_wproj, *p_wout;
    int *p_cnt;
    cudaGetSymbolAddress((void**)&p_cur,   g_cur);
    cudaGetSymbolAddress((void**)&p_mid,   g_mid);
    cudaGetSymbolAddress((void**)&p_x32,   g_x32);
    cudaGetSymbolAddress((void**)&p_hsA,   g_hsA);
    cudaGetSymbolAddress((void**)&p_hsB,   g_hsB);
    cudaGetSymbolAddress((void**)&p_pc,    g_pc);
    cudaGetSymbolAddress((void**)&p_obj32, g_obj32);
    cudaGetSymbolAddress((void**)&p_w1,    g_w1r);
    cudaGetSymbolAddress((void**)&p_w2,    g_w2r);
    cudaGetSymbolAddress((void**)&p_wproj, g_wprojr);
    cudaGetSymbolAddress((void**)&p_wout,  g_woutr);
    cudaGetSymbolAddress((void**)&p_cnt,   g_cnt);

    cudaFuncSetAttribute(tgemm<0, true >, cudaFuncAttributeMaxDynamicSharedMemorySize, TG_SMEM);
    cudaFuncSetAttribute(tgemm<1, true >, cudaFuncAttributeMaxDynamicSharedMemorySize, TG_SMEM);
    cudaFuncSetAttribute(tgemm<2, true >, cudaFuncAttributeMaxDynamicSharedMemorySize, TG_SMEM);
    cudaFuncSetAttribute(tgemm<3, true >, cudaFuncAttributeMaxDynamicSharedMemorySize, TG_SMEM);
    cudaFuncSetAttribute(lstm_step<true >, cudaFuncAttributeMaxDynamicSharedMemorySize, TG_SMEM);
    cudaFuncSetAttribute(lstm_step<false>, cudaFuncAttributeMaxDynamicSharedMemorySize, TG_SMEM);

    const int MT_E = (T_EDGES + 127) / 128;        // 391
    const int MT_O = (O_NODES + 127) / 128;        // 79

    // prep (all weight rounding/permutation + obj round + bias) in one launch
    k_prep<<<(PRE_TOTAL + 255) / 256, 256>>>(W1, W2, Wih, Whh, Wproj, Wout, obj, bih, bhh);

    // node sort by length (descending)
    k_zero_hist<<<HIST_SZ / 256, 256>>>();
    k_hist<<<(O_NODES + 255) / 256, 256>>>(lengths);
    k_scan<<<1, 1>>>(L);
    k_scatter<<<(O_NODES + 255) / 256, 256>>>(lengths);

    // edge MLP; GEMM2 writes new_s/new_o (rounded) to g_x32 and new_p to out
    k_build_cur<<<(T_EDGES * 384 + 255) / 256, 256>>>(obj, pred, edges);
    tgemm<1, true ><<<dim3(4, MT_E), 128, TG_SMEM>>>(p_cur, 384, p_w1, 384, b1,
        p_mid, 512, nullptr, T_EDGES);
    tgemm<2, true ><<<dim3(9, MT_E), 128, TG_SMEM>>>(p_mid, 512, p_w2, 512, b2,
        out + (size_t)O_NODES * 128, 128, p_x32, T_EDGES);

    // prev = obj @ Wproj^T + bproj, written directly into pc cols [512,1024)
    tgemm<3, true ><<<dim3(4, MT_O), 128, TG_SMEM>>>(p_obj32, 128, p_wproj, 128, bproj,
        p_pc + 512, 1024, nullptr, O_NODES);

    // LSTM: step 0 closed form (buffer B); step 1 = x-only GEMM + ghh1 broadcast
    // (buffer A); steps t=2..L-1 fused [h|x] GEMM + pointwise, ping-pong.
    k_step0a<<<1, 512>>>();
    k_step0b<<<(O_NODES * HH + 255) / 256, 256>>>();
    k_ghh1<<<8, 256>>>();
    lstm_step<true ><<<dim3(16, MT_O), 128, TG_SMEM>>>(p_hsB, 1, L, nbr, p_cnt + 1, p_hsA);
    for (int t = 2; t < L; ++t) {
        float* hin  = (t & 1) ? p_hsB : p_hsA;
        float* hout = (t & 1) ? p_hsA : p_hsB;
        lstm_step<false><<<dim3(16, MT_O), 128, TG_SMEM>>>(hin, t, L, nbr, p_cnt + t, hout);
    }

    // pooled half of pc, then new_obj = pc @ Wout^T + bout (exact epilogue)
    k_build_pc_h<<<(O_NODES * 128 + 255) / 256, 256>>>(lengths);
    tgemm<0, true ><<<dim3(1, MT_O), 128, TG_SMEM>>>(p_pc, 1024, p_wout, 1024, bout,
        out, 128, nullptr, O_NODES);
}